// round 15
// baseline (speedup 1.0000x reference)
#include <cuda_runtime.h>
#include <cuda_fp16.h>
#include <math.h>
#include <stdint.h>

#define DD    128
#define HH    8
#define LSEQ  16
#define WWLK  32768
#define NNODE 50000
#define FHID  384
#define WL    (WWLK * LSEQ)   /* 524288 */

/* ------------------------------------------------------------------ */
/* static device scratch (~2.88GB < 4GB aarch64 .bss limit)            */
/* ------------------------------------------------------------------ */
__device__ float g_x  [WL * DD];         /* working x (fp32)          */
__device__ float g_xf [WL * FHID];       /* xi_f / ffn g1 aux / v     */
__device__ float g_xb [WL * FHID];       /* xi_b  (aliased: u halves) */
__device__ float g_e  [WL * HH];
__device__ unsigned int g_menc[NNODE * HH];
__device__ float g_den [NNODE * HH];
__device__ float g_node[NNODE * DD];
__device__ float g_back[NNODE * DD];
__device__ float g_t2  [NNODE * DD];

/* half hi/lo pools */
__device__ __half g_hh [WL * DD],      g_hl [WL * DD];       /* rmsnorm out */
__device__ __half g_hsh[2 * WWLK * DD],g_hsl[2 * WWLK * DD]; /* GRU state   */
__device__ __half g_yh [WL * 2 * DD],  g_yl [WL * 2 * DD];   /* GRU y (aliased: xh/xl) */
__device__ __half g_nh [NNODE * DD],   g_nl [NNODE * DD];    /* node emb    */
__device__ __half g_t1h[NNODE * DD],   g_t1l[NNODE * DD];    /* head h1     */

/* weight half pool */
#define O_WIF 0
#define O_WIB (O_WIF + FHID * DD)
#define O_WHF (O_WIB + FHID * DD)
#define O_WHB (O_WHF + FHID * DD)
#define O_GO  (O_WHB + FHID * DD)
#define O_W1  (O_GO  + DD * 2 * DD)
#define O_W2  (O_W1  + FHID * DD)
#define O_W3  (O_W2  + DD * FHID)
#define O_TO  (O_W3  + FHID * DD)
#define O_FR  (O_TO  + DD * DD)
#define O_HW1 (O_FR  + DD * DD)
#define O_HW2 (O_HW1 + DD * DD)
#define O_END (O_HW2 + DD * DD)
__device__ __half g_wh[O_END], g_wl[O_END];

/* ------------------------------------------------------------------ */
/* PTX helpers                                                         */
/* ------------------------------------------------------------------ */
__device__ __forceinline__ uint32_t smem_u32(const void* p) {
    uint32_t a;
    asm("{ .reg .u64 t; cvta.to.shared.u64 t, %1; cvt.u32.u64 %0, t; }"
        : "=r"(a) : "l"(p));
    return a;
}
__device__ __forceinline__ void cp_async16(uint32_t dst, const void* src, int sz) {
    asm volatile("cp.async.cg.shared.global [%0], [%1], 16, %2;"
                 :: "r"(dst), "l"(src), "r"(sz) : "memory");
}
__device__ __forceinline__ void cp_commit() {
    asm volatile("cp.async.commit_group;" ::: "memory");
}
template <int N>
__device__ __forceinline__ void cp_wait() {
    asm volatile("cp.async.wait_group %0;" :: "n"(N) : "memory");
}
__device__ __forceinline__ void ldm_x4(uint32_t* r, uint32_t addr) {
    asm volatile("ldmatrix.sync.aligned.m8n8.x4.shared.b16 {%0,%1,%2,%3}, [%4];"
                 : "=r"(r[0]), "=r"(r[1]), "=r"(r[2]), "=r"(r[3]) : "r"(addr));
}
__device__ __forceinline__ void ldm_x2(uint32_t* r, uint32_t addr) {
    asm volatile("ldmatrix.sync.aligned.m8n8.x2.shared.b16 {%0,%1}, [%2];"
                 : "=r"(r[0]), "=r"(r[1]) : "r"(addr));
}
__device__ __forceinline__ void mma16816(float* d, const uint32_t* a, const uint32_t* b) {
    asm volatile(
        "mma.sync.aligned.m16n8k16.row.col.f32.f16.f16.f32 "
        "{%0,%1,%2,%3}, {%4,%5,%6,%7}, {%8,%9}, {%0,%1,%2,%3};"
        : "+f"(d[0]), "+f"(d[1]), "+f"(d[2]), "+f"(d[3])
        : "r"(a[0]), "r"(a[1]), "r"(a[2]), "r"(a[3]), "r"(b[0]), "r"(b[1]));
}
__device__ __forceinline__ float sigf(float x) {
    return __fdividef(1.f, 1.f + __expf(-x));
}
__device__ __forceinline__ float tanhfast(float x) {
    x = fminf(fmaxf(x, -15.f), 15.f);
    float e = __expf(-2.f * x);
    return __fdividef(1.f - e, 1.f + e);
}
__device__ __forceinline__ float siluf(float g) {
    return __fdividef(g, 1.f + __expf(-g));
}
__device__ __forceinline__ void splitf(float v, __half& h, __half& l) {
    h = __float2half_rn(v);
    l = __float2half_rn(v - __half2float(h));
}

/* ------------------------------------------------------------------ */
/* 3xFP16 GEMM on pre-split operands, cp.async double-buffered         */
/* C[M,N] = A[M,K] @ B[N,K]^T ; BM=BN=128, BK=32, 256 thr, warp 32x64  */
/* ------------------------------------------------------------------ */
#define MATB   10240            /* 128 rows * 80B */
#define STAGEB (4 * MATB)
#define GSMEM  (2 * STAGEB)     /* 81920 */

__device__ __forceinline__ void issue_stage(
    uint32_t sb, int stage, int k0, int tid,
    const __half* Ahi, const __half* Alo,
    const __half* Bhi, const __half* Blo,
    int bm, int bn, int M, int N, int K)
{
#pragma unroll
    for (int i = 0; i < 8; i++) {
        const int mat = i >> 1;
        const int rem = ((i & 1) << 8) + tid;    /* 0..511 */
        const int row = rem >> 2, c = rem & 3;
        uint32_t dst = sb + stage * STAGEB + mat * MATB + row * 80 + c * 16;
        const __half* base = (mat == 0) ? Ahi : (mat == 1) ? Alo
                           : (mat == 2) ? Bhi : Blo;
        const bool isA = (mat < 2);
        const int gr = (isA ? bm : bn) + row;
        const int lim = isA ? M : N;
        const __half* src = base + (size_t)gr * K + k0 + c * 8;
        cp_async16(dst, src, (gr < lim) ? 16 : 0);
    }
}

template <int MODE>
__global__ void __launch_bounds__(256) hgemm_k(
    const __half* __restrict__ Ahi, const __half* __restrict__ Alo,
    const __half* __restrict__ Bhi, const __half* __restrict__ Blo,
    float* __restrict__ C, __half* __restrict__ Chi, __half* __restrict__ Clo,
    const float* __restrict__ bias, const float* __restrict__ aux,
    int M, int N, int K)
{
    extern __shared__ char smem[];
    const uint32_t sb = smem_u32(smem);
    const int tid = threadIdx.x;
    const int lid = tid & 31, wid = tid >> 5;
    const int bm = blockIdx.y * 128, bn = blockIdx.x * 128;
    const int wm = (wid & 3) * 32, wn = (wid >> 2) * 64;

    float acc[2][8][4];
#pragma unroll
    for (int mt = 0; mt < 2; mt++)
#pragma unroll
        for (int nt = 0; nt < 8; nt++)
#pragma unroll
            for (int r = 0; r < 4; r++) acc[mt][nt][r] = 0.f;

    const int quad = lid >> 3;
    const int a_row_base = wm + ((quad & 1) << 3) + (lid & 7);
    const int a_col_base = (quad >> 1) << 3;
    const int b_row_base = wn + (lid & 7);
    const int b_col_base = ((lid >> 3) & 1) << 3;

    const int nk = K / 32;
    issue_stage(sb, 0, 0, tid, Ahi, Alo, Bhi, Blo, bm, bn, M, N, K);
    cp_commit();

    for (int c = 0; c < nk; c++) {
        if (c + 1 < nk) {
            issue_stage(sb, (c + 1) & 1, (c + 1) * 32, tid,
                        Ahi, Alo, Bhi, Blo, bm, bn, M, N, K);
            cp_commit();
            cp_wait<1>();
        } else {
            cp_wait<0>();
        }
        __syncthreads();

        const uint32_t st = sb + (c & 1) * STAGEB;
        const uint32_t sAh = st, sAl = st + MATB, sBh = st + 2 * MATB, sBl = st + 3 * MATB;
#pragma unroll
        for (int kc2 = 0; kc2 < 2; kc2++) {
            uint32_t ah[2][4], al[2][4];
#pragma unroll
            for (int mt = 0; mt < 2; mt++) {
                uint32_t off = (uint32_t)(a_row_base + mt * 16) * 80u +
                               (uint32_t)(kc2 * 16 + a_col_base) * 2u;
                ldm_x4(ah[mt], sAh + off);
                ldm_x4(al[mt], sAl + off);
            }
#pragma unroll
            for (int nt = 0; nt < 8; nt++) {
                uint32_t off = (uint32_t)(b_row_base + nt * 8) * 80u +
                               (uint32_t)(kc2 * 16 + b_col_base) * 2u;
                uint32_t bh2[2], bl2[2];
                ldm_x2(bh2, sBh + off);
                ldm_x2(bl2, sBl + off);
#pragma unroll
                for (int mt = 0; mt < 2; mt++) {
                    mma16816(acc[mt][nt], ah[mt], bh2);
                    mma16816(acc[mt][nt], ah[mt], bl2);
                    mma16816(acc[mt][nt], al[mt], bh2);
                }
            }
        }
        __syncthreads();
    }

    /* epilogue */
#pragma unroll
    for (int mt = 0; mt < 2; mt++) {
        int r0 = bm + wm + mt * 16 + (lid >> 2);
#pragma unroll
        for (int hf = 0; hf < 2; hf++) {
            int row = r0 + hf * 8;
            if (row >= M) continue;
#pragma unroll
            for (int nt = 0; nt < 8; nt++) {
                int col = bn + wn + nt * 8 + (lid & 3) * 2;
                float v0 = acc[mt][nt][hf * 2 + 0];
                float v1 = acc[mt][nt][hf * 2 + 1];
                size_t off = (size_t)row * N + col;
                if (MODE == 0) {
                    if (bias) { v0 += bias[col]; v1 += bias[col + 1]; }
                } else if (MODE == 1) {
                    float2 cc = *(const float2*)(C + off);
                    v0 += cc.x; v1 += cc.y;
                } else if (MODE == 2) {
                    v0 = fmaxf(v0 + bias[col], 0.f);
                    v1 = fmaxf(v1 + bias[col + 1], 0.f);
                } else if (MODE == 3) {
                    float2 gg = *(const float2*)(aux + off);
                    v0 *= siluf(gg.x); v1 *= siluf(gg.y);
                }
                if (C) *(float2*)(C + off) = make_float2(v0, v1);
                if (Chi) {
                    __half h0, l0, h1, l1;
                    splitf(v0, h0, l0); splitf(v1, h1, l1);
                    *(__half2*)(Chi + off) = __halves2half2(h0, h1);
                    *(__half2*)(Clo + off) = __halves2half2(l0, l1);
                }
            }
        }
    }
}

/* ------------------------------------------------------------------ */
/* fused GRU step: g = h@Wh^T + bh computed with BN=384-wide CTA,      */
/* gates applied in epilogue, state (hi/lo halves) updated in place.   */
/* BM=64, K=128 (4 k-iters, double buffered). 256 threads.             */
/* warps: 2(m)x4(n); each warp's n covers cols wn..wn+32 of ALL three  */
/* gate blocks (r,z,n) so gates close in registers.                    */
/* smem: A-hi 0 (5120B) | A-lo 5120 | B-hi 10240 (30720B) | B-lo 40960 */
/* stage = 71680B, 2 stages = 143360B.                                 */
/* ------------------------------------------------------------------ */
#define GRU_STAGE 71680
#define GRU_SMEM  (2 * GRU_STAGE)

__device__ __forceinline__ void gru_issue(
    uint32_t sb, int stage, int k0, int tid, int bm,
    const __half* Ahi, const __half* Alo,
    const __half* Bhi, const __half* Blo)
{
#pragma unroll
    for (int i = 0; i < 14; i++) {
        int gid = i * 256 + tid;            /* 0..3583 */
        uint32_t dst;
        const __half* src;
        if (gid < 512) {                    /* A: 2 mats x 64 rows x 4 chunks */
            int mat = gid >> 8;
            int r = (gid >> 2) & 63;
            int c = gid & 3;
            dst = sb + stage * GRU_STAGE + mat * 5120 + r * 80 + c * 16;
            src = (mat ? Alo : Ahi) + (size_t)(bm + r) * 128 + k0 + c * 8;
        } else {                            /* B: 2 mats x 384 rows x 4 chunks */
            int bgid = gid - 512;
            int mat = bgid >= 1536;
            int rr = (bgid - mat * 1536) >> 2;
            int c = bgid & 3;
            dst = sb + stage * GRU_STAGE + 10240 + mat * 30720 + rr * 80 + c * 16;
            src = (mat ? Blo : Bhi) + (size_t)rr * 128 + k0 + c * 8;
        }
        cp_async16(dst, src, 16);
    }
}

__global__ void __launch_bounds__(256) gru_step_k(
    __half* __restrict__ hsh, __half* __restrict__ hsl,
    const __half* __restrict__ Wfh, const __half* __restrict__ Wfl,
    const __half* __restrict__ Wbh, const __half* __restrict__ Wbl,
    const float* __restrict__ bhf, const float* __restrict__ bhb,
    const float* __restrict__ xif, const float* __restrict__ xib,
    __half* __restrict__ yh, __half* __restrict__ yl, int step)
{
    extern __shared__ char smem[];
    const uint32_t sb = smem_u32(smem);
    const int tid = threadIdx.x, lid = tid & 31, wid = tid >> 5;
    const int bm = blockIdx.x * 64;
    const int dir = (bm >= WWLK) ? 1 : 0;
    const __half* Bh = dir ? Wbh : Wfh;
    const __half* Bl = dir ? Wbl : Wfl;
    const float* bias = dir ? bhb : bhf;
    const float* xi   = dir ? xib : xif;
    const int l = dir ? (LSEQ - 1 - step) : step;
    const int wrow0 = bm - dir * WWLK;
    const int wm = (wid & 1) * 32, wn = (wid >> 1) * 32;

    float acc[2][12][4];
#pragma unroll
    for (int mt = 0; mt < 2; mt++)
#pragma unroll
        for (int nt = 0; nt < 12; nt++)
#pragma unroll
            for (int r = 0; r < 4; r++) acc[mt][nt][r] = 0.f;

    const int quad = lid >> 3;
    const int a_row_base = wm + ((quad & 1) << 3) + (lid & 7);
    const int a_col_base = (quad >> 1) << 3;
    const int b_row_base = lid & 7;
    const int b_col_base = ((lid >> 3) & 1) << 3;

    gru_issue(sb, 0, 0, tid, bm, hsh, hsl, Bh, Bl);
    cp_commit();

    for (int c4 = 0; c4 < 4; c4++) {
        if (c4 + 1 < 4) {
            gru_issue(sb, (c4 + 1) & 1, (c4 + 1) * 32, tid, bm, hsh, hsl, Bh, Bl);
            cp_commit();
            cp_wait<1>();
        } else {
            cp_wait<0>();
        }
        __syncthreads();

        const uint32_t st = sb + (c4 & 1) * GRU_STAGE;
#pragma unroll
        for (int kc2 = 0; kc2 < 2; kc2++) {
            uint32_t ah[2][4], al[2][4];
#pragma unroll
            for (int mt = 0; mt < 2; mt++) {
                uint32_t off = (uint32_t)(a_row_base + mt * 16) * 80u +
                               (uint32_t)(kc2 * 16 + a_col_base) * 2u;
                ldm_x4(ah[mt], st + off);
                ldm_x4(al[mt], st + 5120 + off);
            }
#pragma unroll
            for (int nb = 0; nb < 3; nb++)
#pragma unroll
                for (int ntf = 0; ntf < 4; ntf++) {
                    int brow = nb * 128 + wn + ntf * 8 + b_row_base;
                    uint32_t off = (uint32_t)brow * 80u +
                                   (uint32_t)(kc2 * 16 + b_col_base) * 2u;
                    uint32_t bh2[2], bl2[2];
                    ldm_x2(bh2, st + 10240 + off);
                    ldm_x2(bl2, st + 40960 + off);
#pragma unroll
                    for (int mt = 0; mt < 2; mt++) {
                        mma16816(acc[mt][nb * 4 + ntf], ah[mt], bh2);
                        mma16816(acc[mt][nb * 4 + ntf], ah[mt], bl2);
                        mma16816(acc[mt][nb * 4 + ntf], al[mt], bh2);
                    }
                }
        }
        __syncthreads();
    }

    /* gate epilogue */
#pragma unroll
    for (int mt = 0; mt < 2; mt++) {
        int rb = wm + mt * 16 + (lid >> 2);
#pragma unroll
        for (int hf = 0; hf < 2; hf++) {
            int r = rb + hf * 8;             /* 0..63 within CTA */
            int row = bm + r;                /* global state row */
            int w = wrow0 + r;               /* walk index */
            size_t xirow = ((size_t)w * LSEQ + l) * FHID;
#pragma unroll
            for (int ntf = 0; ntf < 4; ntf++) {
                int d = wn + ntf * 8 + (lid & 3) * 2;
                float2 xr = *(const float2*)(xi + xirow + d);
                float2 xz = *(const float2*)(xi + xirow + 128 + d);
                float2 xn = *(const float2*)(xi + xirow + 256 + d);
                float2 br = *(const float2*)(bias + d);
                float2 bz = *(const float2*)(bias + 128 + d);
                float2 bn = *(const float2*)(bias + 256 + d);
                __half2 hh2 = *(const __half2*)(hsh + (size_t)row * DD + d);
                __half2 hl2 = *(const __half2*)(hsl + (size_t)row * DD + d);
                float h0 = __half2float(__low2half(hh2)) + __half2float(__low2half(hl2));
                float h1 = __half2float(__high2half(hh2)) + __half2float(__high2half(hl2));

                float hr0 = acc[mt][0 + ntf][hf * 2 + 0] + br.x;
                float hr1 = acc[mt][0 + ntf][hf * 2 + 1] + br.y;
                float hz0 = acc[mt][4 + ntf][hf * 2 + 0] + bz.x;
                float hz1 = acc[mt][4 + ntf][hf * 2 + 1] + bz.y;
                float hn0 = acc[mt][8 + ntf][hf * 2 + 0] + bn.x;
                float hn1 = acc[mt][8 + ntf][hf * 2 + 1] + bn.y;

                float rg0 = sigf(xr.x + hr0), rg1 = sigf(xr.y + hr1);
                float z0  = sigf(xz.x + hz0), z1  = sigf(xz.y + hz1);
                float n0  = tanhfast(xn.x + rg0 * hn0);
                float n1  = tanhfast(xn.y + rg1 * hn1);
                float o0 = (1.f - z0) * n0 + z0 * h0;
                float o1 = (1.f - z1) * n1 + z1 * h1;

                __half h0h, h0l, h1h, h1l;
                splitf(o0, h0h, h0l);
                splitf(o1, h1h, h1l);
                *(__half2*)(hsh + (size_t)row * DD + d) = __halves2half2(h0h, h1h);
                *(__half2*)(hsl + (size_t)row * DD + d) = __halves2half2(h0l, h1l);
                size_t yoff = ((size_t)w * LSEQ + l) * (2 * DD) + dir * DD + d;
                *(__half2*)(yh + yoff) = __halves2half2(h0h, h1h);
                *(__half2*)(yl + yoff) = __halves2half2(h0l, h1l);
            }
        }
    }
}

/* ------------------------------------------------------------------ */
/* elementwise kernels                                                 */
/* ------------------------------------------------------------------ */
__global__ void split_k(const float* __restrict__ src, __half* __restrict__ hi,
                        __half* __restrict__ lo, int n)
{
    int i = blockIdx.x * blockDim.x + threadIdx.x;
    if (i >= n) return;
    __half h, l;
    splitf(src[i], h, l);
    hi[i] = h; lo[i] = l;
}

__global__ void rmsnorm_k(const float* __restrict__ x, const float* __restrict__ w,
                          __half* __restrict__ ohi, __half* __restrict__ olo, int rows)
{
    int row = blockIdx.x * 8 + (threadIdx.x >> 5);
    int lane = threadIdx.x & 31;
    if (row >= rows) return;
    float4 v = ((const float4*)(x + (size_t)row * DD))[lane];
    float ss = v.x * v.x + v.y * v.y + v.z * v.z + v.w * v.w;
#pragma unroll
    for (int o = 16; o; o >>= 1) ss += __shfl_xor_sync(~0u, ss, o);
    float r = rsqrtf(ss * (1.f / 128.f) + 1e-5f);
    float4 wv = ((const float4*)w)[lane];
    float o0 = v.x * r * wv.x, o1 = v.y * r * wv.y;
    float o2 = v.z * r * wv.z, o3 = v.w * r * wv.w;
    __half h0, l0, h1, l1, h2, l2, h3, l3;
    splitf(o0, h0, l0); splitf(o1, h1, l1);
    splitf(o2, h2, l2); splitf(o3, h3, l3);
    size_t base = (size_t)row * DD + lane * 4;
    *(__half2*)(ohi + base)     = __halves2half2(h0, h1);
    *(__half2*)(ohi + base + 2) = __halves2half2(h2, h3);
    *(__half2*)(olo + base)     = __halves2half2(l0, l1);
    *(__half2*)(olo + base + 2) = __halves2half2(l2, l3);
}

__global__ void logits_k(const float* __restrict__ x, const float* __restrict__ lw,
                         const float* __restrict__ lb, float* __restrict__ out, int rows)
{
    int row = blockIdx.x * 8 + (threadIdx.x >> 5);
    int lane = threadIdx.x & 31;
    if (row >= rows) return;
    float4 v = ((const float4*)(x + (size_t)row * DD))[lane];
#pragma unroll
    for (int h = 0; h < HH; h++) {
        float4 w = ((const float4*)(lw + (size_t)h * DD))[lane];
        float p = v.x * w.x + v.y * w.y + v.z * w.z + v.w * w.w;
#pragma unroll
        for (int o = 16; o; o >>= 1) p += __shfl_xor_sync(~0u, p, o);
        if (!lane) out[(size_t)row * HH + h] = p + lb[h];
    }
}

__device__ __forceinline__ unsigned fenc(float f)
{
    unsigned u = __float_as_uint(f);
    return (u & 0x80000000u) ? ~u : (u | 0x80000000u);
}

__global__ void segmax_k(const float* __restrict__ lg, const int* __restrict__ seg,
                         unsigned* __restrict__ menc, int total)
{
    int i = blockIdx.x * blockDim.x + threadIdx.x;
    if (i >= total) return;
    int row = i >> 3, h = i & 7;
    atomicMax(&menc[(size_t)seg[row] * HH + h], fenc(lg[i]));
}

__global__ void expden_k(float* __restrict__ lg, const int* __restrict__ seg,
                         const unsigned* __restrict__ menc, float* __restrict__ den, int total)
{
    int i = blockIdx.x * blockDim.x + threadIdx.x;
    if (i >= total) return;
    int row = i >> 3, h = i & 7;
    unsigned u = menc[(size_t)seg[row] * HH + h];
    float m = 0.f;
    if (u) {
        unsigned b = (u & 0x80000000u) ? (u ^ 0x80000000u) : ~u;
        m = __uint_as_float(b);
    }
    float e = __expf(lg[i] - m);
    lg[i] = e;
    atomicAdd(&den[(size_t)seg[row] * HH + h], e);
}

__global__ void scatter_k(const float* __restrict__ e, const float* __restrict__ den,
                          const float* __restrict__ v, const int* __restrict__ seg,
                          float* __restrict__ node, int total)
{
    int i = blockIdx.x * blockDim.x + threadIdx.x;
    if (i >= total) return;
    int row = i >> 7, d = i & 127;
    int nd = seg[row];
    int h = d >> 4;
    float a = e[(size_t)row * HH + h] / (den[(size_t)nd * HH + h] + 1e-9f);
    atomicAdd(&node[(size_t)nd * DD + d], a * v[i]);
}

__global__ void addback_k(float* __restrict__ x, const float* __restrict__ back,
                          const int* __restrict__ seg, int total)
{
    int i = blockIdx.x * blockDim.x + threadIdx.x;
    if (i >= total) return;
    int row = i >> 7, d = i & 127;
    x[i] += back[(size_t)seg[row] * DD + d];
}

__global__ void headout_k(const float* __restrict__ h2, const float* __restrict__ w3,
                          const float* __restrict__ b3, float* __restrict__ out)
{
    int row = blockIdx.x * 8 + (threadIdx.x >> 5);
    int lane = threadIdx.x & 31;
    if (row >= NNODE) return;
    float4 v = ((const float4*)(h2 + (size_t)row * DD))[lane];
    float4 w = ((const float4*)w3)[lane];
    float p = v.x * w.x + v.y * w.y + v.z * w.z + v.w * w.w;
#pragma unroll
    for (int o = 16; o; o >>= 1) p += __shfl_xor_sync(~0u, p, o);
    if (!lane) out[row] = p + b3[0];
}

/* ------------------------------------------------------------------ */
/* orchestration                                                       */
/* ------------------------------------------------------------------ */
static inline void hgemm(int mode,
    const __half* Ahi, const __half* Alo, const __half* Bhi, const __half* Blo,
    float* C, __half* Chi, __half* Clo,
    const float* bias, const float* aux, int M, int N, int K)
{
    dim3 grid((N + 127) / 128, (M + 127) / 128);
    switch (mode) {
        case 0: hgemm_k<0><<<grid, 256, GSMEM>>>(Ahi, Alo, Bhi, Blo, C, Chi, Clo, bias, aux, M, N, K); break;
        case 1: hgemm_k<1><<<grid, 256, GSMEM>>>(Ahi, Alo, Bhi, Blo, C, Chi, Clo, bias, aux, M, N, K); break;
        case 2: hgemm_k<2><<<grid, 256, GSMEM>>>(Ahi, Alo, Bhi, Blo, C, Chi, Clo, bias, aux, M, N, K); break;
        case 3: hgemm_k<3><<<grid, 256, GSMEM>>>(Ahi, Alo, Bhi, Blo, C, Chi, Clo, bias, aux, M, N, K); break;
    }
}

extern "C" void kernel_launch(void* const* d_in, const int* in_sizes, int n_in,
                              void* d_out, int out_size)
{
    cudaFuncSetAttribute(hgemm_k<0>, cudaFuncAttributeMaxDynamicSharedMemorySize, GSMEM);
    cudaFuncSetAttribute(hgemm_k<1>, cudaFuncAttributeMaxDynamicSharedMemorySize, GSMEM);
    cudaFuncSetAttribute(hgemm_k<2>, cudaFuncAttributeMaxDynamicSharedMemorySize, GSMEM);
    cudaFuncSetAttribute(hgemm_k<3>, cudaFuncAttributeMaxDynamicSharedMemorySize, GSMEM);
    cudaFuncSetAttribute(gru_step_k, cudaFuncAttributeMaxDynamicSharedMemorySize, GRU_SMEM);

    int shift = (n_in >= 3 && in_sizes[2] == 1) ? 0 : -1;
#define FIN(i) ((const float*)d_in[(i) >= 3 ? (i) + shift : (i)])
    const float* x_in       = (const float*)d_in[0];
    const int*   walk       = (const int*)d_in[1];
    const float* gru_norm_w = FIN(3);
    const float* wi_f = FIN(4),  *wh_f = FIN(5),  *bi_f = FIN(6),  *bh_f = FIN(7);
    const float* wi_b = FIN(8),  *wh_b = FIN(9),  *bi_b = FIN(10), *bh_b = FIN(11);
    const float* gru_out_w = FIN(12);
    const float* ffn_norm_w = FIN(13);
    const float* w1 = FIN(14), *w2 = FIN(15), *w3 = FIN(16);
    const float* logit_w = FIN(17), *logit_b = FIN(18);
    const float* to_w = FIN(19), *to_b = FIN(20);
    const float* fr_w = FIN(21), *fr_b = FIN(22);
    const float* hw1 = FIN(23), *hb1 = FIN(24);
    const float* hw2 = FIN(25), *hb2 = FIN(26);
    const float* hw3 = FIN(27), *hb3 = FIN(28);
#undef FIN

    float *px, *pxf, *pxb, *pe, *pden, *pnode, *pback, *pt2;
    unsigned* pmenc;
    __half *phh, *phl, *phsh, *phsl, *pyh, *pyl;
    __half *pnh, *pnl, *pt1h, *pt1l, *pwh, *pwl;
    cudaGetSymbolAddress((void**)&px,   g_x);
    cudaGetSymbolAddress((void**)&pxf,  g_xf);
    cudaGetSymbolAddress((void**)&pxb,  g_xb);
    cudaGetSymbolAddress((void**)&pe,   g_e);
    cudaGetSymbolAddress((void**)&pmenc, g_menc);
    cudaGetSymbolAddress((void**)&pden, g_den);
    cudaGetSymbolAddress((void**)&pnode, g_node);
    cudaGetSymbolAddress((void**)&pback, g_back);
    cudaGetSymbolAddress((void**)&pt2,  g_t2);
    cudaGetSymbolAddress((void**)&phh,  g_hh);
    cudaGetSymbolAddress((void**)&phl,  g_hl);
    cudaGetSymbolAddress((void**)&phsh, g_hsh);
    cudaGetSymbolAddress((void**)&phsl, g_hsl);
    cudaGetSymbolAddress((void**)&pyh,  g_yh);
    cudaGetSymbolAddress((void**)&pyl,  g_yl);
    cudaGetSymbolAddress((void**)&pnh,  g_nh);
    cudaGetSymbolAddress((void**)&pnl,  g_nl);
    cudaGetSymbolAddress((void**)&pt1h, g_t1h);
    cudaGetSymbolAddress((void**)&pt1l, g_t1l);
    cudaGetSymbolAddress((void**)&pwh,  g_wh);
    cudaGetSymbolAddress((void**)&pwl,  g_wl);

    /* lifetime aliases: */
    float* pv   = pxf;                                  /* v over dead g1 aux   */
    __half* puh = (__half*)pxb;                         /* u.hi over dead xi_b  */
    __half* pul = (__half*)pxb + (size_t)WL * FHID;     /* u.lo                 */
    __half* pxh = pyh;                                  /* x.hi over dead y.hi  */
    __half* pxl = pyl;                                  /* x.lo over dead y.lo  */

    /* split all weights into half hi/lo pools */
    struct { const float* s; int off; int n; } ws[] = {
        { wi_f, O_WIF, FHID * DD }, { wi_b, O_WIB, FHID * DD },
        { wh_f, O_WHF, FHID * DD }, { wh_b, O_WHB, FHID * DD },
        { gru_out_w, O_GO, DD * 2 * DD },
        { w1, O_W1, FHID * DD }, { w2, O_W2, DD * FHID }, { w3, O_W3, FHID * DD },
        { to_w, O_TO, DD * DD }, { fr_w, O_FR, DD * DD },
        { hw1, O_HW1, DD * DD }, { hw2, O_HW2, DD * DD },
    };
    for (int i = 0; i < 12; i++)
        split_k<<<(ws[i].n + 255) / 256, 256>>>(ws[i].s, pwh + ws[i].off, pwl + ws[i].off, ws[i].n);

    cudaMemcpyAsync(px, x_in, (size_t)WL * DD * sizeof(float), cudaMemcpyDeviceToDevice);

    const int totWH = WL * HH;
    const int totWD = WL * DD;

    for (int t = 0; t < 2; t++) {
        /* ---- Bidirectional GRU block ---- */
        rmsnorm_k<<<WL / 8, 256>>>(px, gru_norm_w, phh, phl, WL);
        hgemm(0, phh, phl, pwh + O_WIF, pwl + O_WIF, pxf, nullptr, nullptr, bi_f, nullptr, WL, FHID, DD);
        hgemm(0, phh, phl, pwh + O_WIB, pwl + O_WIB, pxb, nullptr, nullptr, bi_b, nullptr, WL, FHID, DD);

        cudaMemsetAsync(phsh, 0, (size_t)2 * WWLK * DD * sizeof(__half));
        cudaMemsetAsync(phsl, 0, (size_t)2 * WWLK * DD * sizeof(__half));
        for (int step = 0; step < LSEQ; step++) {
            gru_step_k<<<2 * WWLK / 64, 256, GRU_SMEM>>>(
                phsh, phsl,
                pwh + O_WHF, pwl + O_WHF, pwh + O_WHB, pwl + O_WHB,
                bh_f, bh_b, pxf, pxb, pyh, pyl, step);
        }
        hgemm(1, pyh, pyl, pwh + O_GO, pwl + O_GO, px, nullptr, nullptr,
              nullptr, nullptr, WL, DD, 2 * DD);

        /* ---- FFN ---- */
        rmsnorm_k<<<WL / 8, 256>>>(px, ffn_norm_w, phh, phl, WL);
        hgemm(0, phh, phl, pwh + O_W1, pwl + O_W1, pxf, nullptr, nullptr,
              nullptr, nullptr, WL, FHID, DD);
        hgemm(3, phh, phl, pwh + O_W3, pwl + O_W3, nullptr, puh, pul,
              nullptr, pxf, WL, FHID, DD);
        hgemm(1, puh, pul, pwh + O_W2, pwl + O_W2, px, pxh, pxl,
              nullptr, nullptr, WL, DD, FHID);

        /* ---- attention scatter ---- */
        logits_k<<<WL / 8, 256>>>(px, logit_w, logit_b, pe, WL);
        cudaMemsetAsync(pmenc, 0, (size_t)NNODE * HH * sizeof(unsigned));
        cudaMemsetAsync(pden,  0, (size_t)NNODE * HH * sizeof(float));
        cudaMemsetAsync(pnode, 0, (size_t)NNODE * DD * sizeof(float));
        segmax_k<<<(totWH + 255) / 256, 256>>>(pe, walk, pmenc, totWH);
        expden_k<<<(totWH + 255) / 256, 256>>>(pe, walk, pmenc, pden, totWH);
        hgemm(0, pxh, pxl, pwh + O_TO, pwl + O_TO, pv, nullptr, nullptr,
              to_b, nullptr, WL, DD, DD);
        scatter_k<<<(totWD + 255) / 256, 256>>>(pe, pden, pv, walk, pnode, totWD);
        split_k<<<(NNODE * DD + 255) / 256, 256>>>(pnode, pnh, pnl, NNODE * DD);
        hgemm(0, pnh, pnl, pwh + O_FR, pwl + O_FR, pback, nullptr, nullptr,
              fr_b, nullptr, NNODE, DD, DD);
        addback_k<<<(totWD + 255) / 256, 256>>>(px, pback, walk, totWD);
    }

    /* ---- scoring head ---- */
    hgemm(2, pnh, pnl, pwh + O_HW1, pwl + O_HW1, nullptr, pt1h, pt1l,
          hb1, nullptr, NNODE, DD, DD);
    hgemm(2, pt1h, pt1l, pwh + O_HW2, pwl + O_HW2, pt2, nullptr, nullptr,
          hb2, nullptr, NNODE, DD, DD);
    headout_k<<<(NNODE + 7) / 8, 256>>>(pt2, hw3, hb3, (float*)d_out);
}

// round 16
// speedup vs baseline: 1.6520x; 1.6520x over previous
#include <cuda_runtime.h>
#include <cuda_fp16.h>
#include <math.h>
#include <stdint.h>

#define DD    128
#define HH    8
#define LSEQ  16
#define WWLK  32768
#define NNODE 50000
#define FHID  384
#define WL    (WWLK * LSEQ)   /* 524288 */

/* ------------------------------------------------------------------ */
/* static device scratch (~2.96GB, < 4GB aarch64 .bss limit)           */
/* ------------------------------------------------------------------ */
__device__ float g_x  [WL * DD];         /* working x (fp32)          */
__device__ float g_xf [WL * FHID];       /* xi_f / ffn g1 aux / v     */
__device__ float g_xb [WL * FHID];       /* xi_b  (aliased: u halves) */
__device__ float g_hs [2 * WWLK * DD];   /* GRU state fp32            */
__device__ float g_g  [2 * WWLK * FHID]; /* GRU gate preacts          */
__device__ float g_e  [WL * HH];
__device__ unsigned int g_menc[NNODE * HH];
__device__ float g_den [NNODE * HH];
__device__ float g_node[NNODE * DD];
__device__ float g_back[NNODE * DD];
__device__ float g_t2  [NNODE * DD];

/* half hi/lo pools */
__device__ __half g_hh [WL * DD],      g_hl [WL * DD];       /* rmsnorm out */
__device__ __half g_hsh[2 * WWLK * DD],g_hsl[2 * WWLK * DD]; /* GRU state   */
__device__ __half g_yh [WL * 2 * DD],  g_yl [WL * 2 * DD];   /* GRU y (aliased: xh/xl) */
__device__ __half g_nh [NNODE * DD],   g_nl [NNODE * DD];    /* node emb    */
__device__ __half g_t1h[NNODE * DD],   g_t1l[NNODE * DD];    /* head h1     */

/* weight half pool */
#define O_WIF 0
#define O_WIB (O_WIF + FHID * DD)
#define O_WHF (O_WIB + FHID * DD)
#define O_WHB (O_WHF + FHID * DD)
#define O_GO  (O_WHB + FHID * DD)
#define O_W1  (O_GO  + DD * 2 * DD)
#define O_W2  (O_W1  + FHID * DD)
#define O_W3  (O_W2  + DD * FHID)
#define O_TO  (O_W3  + FHID * DD)
#define O_FR  (O_TO  + DD * DD)
#define O_HW1 (O_FR  + DD * DD)
#define O_HW2 (O_HW1 + DD * DD)
#define O_END (O_HW2 + DD * DD)
__device__ __half g_wh[O_END], g_wl[O_END];

/* ------------------------------------------------------------------ */
/* PTX helpers                                                         */
/* ------------------------------------------------------------------ */
__device__ __forceinline__ uint32_t smem_u32(const void* p) {
    uint32_t a;
    asm("{ .reg .u64 t; cvta.to.shared.u64 t, %1; cvt.u32.u64 %0, t; }"
        : "=r"(a) : "l"(p));
    return a;
}
__device__ __forceinline__ void cp_async16(uint32_t dst, const void* src, int sz) {
    asm volatile("cp.async.cg.shared.global [%0], [%1], 16, %2;"
                 :: "r"(dst), "l"(src), "r"(sz) : "memory");
}
__device__ __forceinline__ void cp_commit() {
    asm volatile("cp.async.commit_group;" ::: "memory");
}
template <int N>
__device__ __forceinline__ void cp_wait() {
    asm volatile("cp.async.wait_group %0;" :: "n"(N) : "memory");
}
__device__ __forceinline__ void ldm_x4(uint32_t* r, uint32_t addr) {
    asm volatile("ldmatrix.sync.aligned.m8n8.x4.shared.b16 {%0,%1,%2,%3}, [%4];"
                 : "=r"(r[0]), "=r"(r[1]), "=r"(r[2]), "=r"(r[3]) : "r"(addr));
}
__device__ __forceinline__ void ldm_x2(uint32_t* r, uint32_t addr) {
    asm volatile("ldmatrix.sync.aligned.m8n8.x2.shared.b16 {%0,%1}, [%2];"
                 : "=r"(r[0]), "=r"(r[1]) : "r"(addr));
}
__device__ __forceinline__ void mma16816(float* d, const uint32_t* a, const uint32_t* b) {
    asm volatile(
        "mma.sync.aligned.m16n8k16.row.col.f32.f16.f16.f32 "
        "{%0,%1,%2,%3}, {%4,%5,%6,%7}, {%8,%9}, {%0,%1,%2,%3};"
        : "+f"(d[0]), "+f"(d[1]), "+f"(d[2]), "+f"(d[3])
        : "r"(a[0]), "r"(a[1]), "r"(a[2]), "r"(a[3]), "r"(b[0]), "r"(b[1]));
}
__device__ __forceinline__ float sigf(float x) {
    return __fdividef(1.f, 1.f + __expf(-x));
}
__device__ __forceinline__ float tanhfast(float x) {
    x = fminf(fmaxf(x, -15.f), 15.f);
    float e = __expf(-2.f * x);
    return __fdividef(1.f - e, 1.f + e);
}
__device__ __forceinline__ float siluf(float g) {
    return __fdividef(g, 1.f + __expf(-g));
}
__device__ __forceinline__ void splitf(float v, __half& h, __half& l) {
    h = __float2half_rn(v);
    l = __float2half_rn(v - __half2float(h));
}

/* ------------------------------------------------------------------ */
/* 3xFP16 GEMM on pre-split operands, cp.async double-buffered         */
/* C[M,N] = A[M,K] @ B[N,K]^T ; BM=BN=128, BK=32, 256 thr, warp 32x64  */
/* ------------------------------------------------------------------ */
#define MATB   10240            /* 128 rows * 80B */
#define STAGEB (4 * MATB)
#define GSMEM  (2 * STAGEB)     /* 81920 */

__device__ __forceinline__ void issue_stage(
    uint32_t sb, int stage, int k0, int tid,
    const __half* Ahi, const __half* Alo,
    const __half* Bhi, const __half* Blo,
    int bm, int bn, int M, int N, int K)
{
#pragma unroll
    for (int i = 0; i < 8; i++) {
        const int mat = i >> 1;
        const int rem = ((i & 1) << 8) + tid;    /* 0..511 */
        const int row = rem >> 2, c = rem & 3;
        uint32_t dst = sb + stage * STAGEB + mat * MATB + row * 80 + c * 16;
        const __half* base = (mat == 0) ? Ahi : (mat == 1) ? Alo
                           : (mat == 2) ? Bhi : Blo;
        const bool isA = (mat < 2);
        const int gr = (isA ? bm : bn) + row;
        const int lim = isA ? M : N;
        const __half* src = base + (size_t)gr * K + k0 + c * 8;
        cp_async16(dst, src, (gr < lim) ? 16 : 0);
    }
}

template <int MODE>
__global__ void __launch_bounds__(256) hgemm_k(
    const __half* __restrict__ Ahi, const __half* __restrict__ Alo,
    const __half* __restrict__ Bhi, const __half* __restrict__ Blo,
    float* __restrict__ C, __half* __restrict__ Chi, __half* __restrict__ Clo,
    const float* __restrict__ bias, const float* __restrict__ aux,
    int M, int N, int K,
    const __half* __restrict__ B2hi, const __half* __restrict__ B2lo,
    const float* __restrict__ bias2, int rowsSplit)
{
    extern __shared__ char smem[];
    const uint32_t sb = smem_u32(smem);
    const int tid = threadIdx.x;
    const int lid = tid & 31, wid = tid >> 5;
    const int bm = blockIdx.y * 128, bn = blockIdx.x * 128;
    if (rowsSplit && bm >= rowsSplit) { Bhi = B2hi; Blo = B2lo; bias = bias2; }
    const int wm = (wid & 3) * 32, wn = (wid >> 2) * 64;

    float acc[2][8][4];
#pragma unroll
    for (int mt = 0; mt < 2; mt++)
#pragma unroll
        for (int nt = 0; nt < 8; nt++)
#pragma unroll
            for (int r = 0; r < 4; r++) acc[mt][nt][r] = 0.f;

    const int quad = lid >> 3;
    const int a_row_base = wm + ((quad & 1) << 3) + (lid & 7);
    const int a_col_base = (quad >> 1) << 3;
    const int b_row_base = wn + (lid & 7);
    const int b_col_base = ((lid >> 3) & 1) << 3;

    const int nk = K / 32;
    issue_stage(sb, 0, 0, tid, Ahi, Alo, Bhi, Blo, bm, bn, M, N, K);
    cp_commit();

    for (int c = 0; c < nk; c++) {
        if (c + 1 < nk) {
            issue_stage(sb, (c + 1) & 1, (c + 1) * 32, tid,
                        Ahi, Alo, Bhi, Blo, bm, bn, M, N, K);
            cp_commit();
            cp_wait<1>();
        } else {
            cp_wait<0>();
        }
        __syncthreads();

        const uint32_t st = sb + (c & 1) * STAGEB;
        const uint32_t sAh = st, sAl = st + MATB, sBh = st + 2 * MATB, sBl = st + 3 * MATB;
#pragma unroll
        for (int kc2 = 0; kc2 < 2; kc2++) {
            uint32_t ah[2][4], al[2][4];
#pragma unroll
            for (int mt = 0; mt < 2; mt++) {
                uint32_t off = (uint32_t)(a_row_base + mt * 16) * 80u +
                               (uint32_t)(kc2 * 16 + a_col_base) * 2u;
                ldm_x4(ah[mt], sAh + off);
                ldm_x4(al[mt], sAl + off);
            }
#pragma unroll
            for (int nt = 0; nt < 8; nt++) {
                uint32_t off = (uint32_t)(b_row_base + nt * 8) * 80u +
                               (uint32_t)(kc2 * 16 + b_col_base) * 2u;
                uint32_t bh2[2], bl2[2];
                ldm_x2(bh2, sBh + off);
                ldm_x2(bl2, sBl + off);
#pragma unroll
                for (int mt = 0; mt < 2; mt++) {
                    mma16816(acc[mt][nt], ah[mt], bh2);
                    mma16816(acc[mt][nt], ah[mt], bl2);
                    mma16816(acc[mt][nt], al[mt], bh2);
                }
            }
        }
        __syncthreads();
    }

    /* epilogue */
#pragma unroll
    for (int mt = 0; mt < 2; mt++) {
        int r0 = bm + wm + mt * 16 + (lid >> 2);
#pragma unroll
        for (int hf = 0; hf < 2; hf++) {
            int row = r0 + hf * 8;
            if (row >= M) continue;
#pragma unroll
            for (int nt = 0; nt < 8; nt++) {
                int col = bn + wn + nt * 8 + (lid & 3) * 2;
                float v0 = acc[mt][nt][hf * 2 + 0];
                float v1 = acc[mt][nt][hf * 2 + 1];
                size_t off = (size_t)row * N + col;
                if (MODE == 0) {
                    if (bias) { v0 += bias[col]; v1 += bias[col + 1]; }
                } else if (MODE == 1) {
                    float2 cc = *(const float2*)(C + off);
                    v0 += cc.x; v1 += cc.y;
                } else if (MODE == 2) {
                    v0 = fmaxf(v0 + bias[col], 0.f);
                    v1 = fmaxf(v1 + bias[col + 1], 0.f);
                } else if (MODE == 3) {
                    float2 gg = *(const float2*)(aux + off);
                    v0 *= siluf(gg.x); v1 *= siluf(gg.y);
                }
                if (C) *(float2*)(C + off) = make_float2(v0, v1);
                if (Chi) {
                    __half h0, l0, h1, l1;
                    splitf(v0, h0, l0); splitf(v1, h1, l1);
                    *(__half2*)(Chi + off) = __halves2half2(h0, h1);
                    *(__half2*)(Clo + off) = __halves2half2(l0, l1);
                }
            }
        }
    }
}

/* ------------------------------------------------------------------ */
/* elementwise kernels                                                 */
/* ------------------------------------------------------------------ */
__global__ void split_k(const float* __restrict__ src, __half* __restrict__ hi,
                        __half* __restrict__ lo, int n)
{
    int i = blockIdx.x * blockDim.x + threadIdx.x;
    if (i >= n) return;
    __half h, l;
    splitf(src[i], h, l);
    hi[i] = h; lo[i] = l;
}

__global__ void rmsnorm_k(const float* __restrict__ x, const float* __restrict__ w,
                          __half* __restrict__ ohi, __half* __restrict__ olo, int rows)
{
    int row = blockIdx.x * 8 + (threadIdx.x >> 5);
    int lane = threadIdx.x & 31;
    if (row >= rows) return;
    float4 v = ((const float4*)(x + (size_t)row * DD))[lane];
    float ss = v.x * v.x + v.y * v.y + v.z * v.z + v.w * v.w;
#pragma unroll
    for (int o = 16; o; o >>= 1) ss += __shfl_xor_sync(~0u, ss, o);
    float r = rsqrtf(ss * (1.f / 128.f) + 1e-5f);
    float4 wv = ((const float4*)w)[lane];
    float o0 = v.x * r * wv.x, o1 = v.y * r * wv.y;
    float o2 = v.z * r * wv.z, o3 = v.w * r * wv.w;
    __half h0, l0, h1, l1, h2, l2, h3, l3;
    splitf(o0, h0, l0); splitf(o1, h1, l1);
    splitf(o2, h2, l2); splitf(o3, h3, l3);
    size_t base = (size_t)row * DD + lane * 4;
    *(__half2*)(ohi + base)     = __halves2half2(h0, h1);
    *(__half2*)(ohi + base + 2) = __halves2half2(h2, h3);
    *(__half2*)(olo + base)     = __halves2half2(l0, l1);
    *(__half2*)(olo + base + 2) = __halves2half2(l2, l3);
}

__global__ void gru_gates_k(const float* __restrict__ xif, const float* __restrict__ xib,
                            const float* __restrict__ g, float* __restrict__ hs,
                            __half* __restrict__ hsh, __half* __restrict__ hsl,
                            __half* __restrict__ yh, __half* __restrict__ yl, int step)
{
    int i = blockIdx.x * blockDim.x + threadIdx.x;
    if (i >= 2 * WWLK * DD) return;
    int dir = i / (WWLK * DD);
    int rem = i - dir * (WWLK * DD);
    int w = rem >> 7, d = rem & 127;
    int l = dir ? (LSEQ - 1 - step) : step;
    const float* xi = dir ? xib : xif;
    size_t xrow = ((size_t)w * LSEQ + l) * FHID;
    float xr = xi[xrow + d], xz = xi[xrow + DD + d], xn = xi[xrow + 2 * DD + d];
    size_t grow = ((size_t)dir * WWLK + w) * FHID;
    float hr = g[grow + d], hz = g[grow + DD + d], hn = g[grow + 2 * DD + d];
    size_t hoff = ((size_t)dir * WWLK + w) * DD + d;
    float h = hs[hoff];
    float rg = sigf(xr + hr);
    float z  = sigf(xz + hz);
    float n  = tanhfast(xn + rg * hn);
    float hnew = (1.f - z) * n + z * h;
    hs[hoff] = hnew;
    __half hh, hl;
    splitf(hnew, hh, hl);
    hsh[hoff] = hh; hsl[hoff] = hl;
    size_t yoff = ((size_t)w * LSEQ + l) * (2 * DD) + dir * DD + d;
    yh[yoff] = hh; yl[yoff] = hl;
}

__global__ void logits_k(const float* __restrict__ x, const float* __restrict__ lw,
                         const float* __restrict__ lb, float* __restrict__ out, int rows)
{
    int row = blockIdx.x * 8 + (threadIdx.x >> 5);
    int lane = threadIdx.x & 31;
    if (row >= rows) return;
    float4 v = ((const float4*)(x + (size_t)row * DD))[lane];
#pragma unroll
    for (int h = 0; h < HH; h++) {
        float4 w = ((const float4*)(lw + (size_t)h * DD))[lane];
        float p = v.x * w.x + v.y * w.y + v.z * w.z + v.w * w.w;
#pragma unroll
        for (int o = 16; o; o >>= 1) p += __shfl_xor_sync(~0u, p, o);
        if (!lane) out[(size_t)row * HH + h] = p + lb[h];
    }
}

__device__ __forceinline__ unsigned fenc(float f)
{
    unsigned u = __float_as_uint(f);
    return (u & 0x80000000u) ? ~u : (u | 0x80000000u);
}

__global__ void segmax_k(const float* __restrict__ lg, const int* __restrict__ seg,
                         unsigned* __restrict__ menc, int total)
{
    int i = blockIdx.x * blockDim.x + threadIdx.x;
    if (i >= total) return;
    int row = i >> 3, h = i & 7;
    atomicMax(&menc[(size_t)seg[row] * HH + h], fenc(lg[i]));
}

__global__ void expden_k(float* __restrict__ lg, const int* __restrict__ seg,
                         const unsigned* __restrict__ menc, float* __restrict__ den, int total)
{
    int i = blockIdx.x * blockDim.x + threadIdx.x;
    if (i >= total) return;
    int row = i >> 3, h = i & 7;
    unsigned u = menc[(size_t)seg[row] * HH + h];
    float m = 0.f;
    if (u) {
        unsigned b = (u & 0x80000000u) ? (u ^ 0x80000000u) : ~u;
        m = __uint_as_float(b);
    }
    float e = __expf(lg[i] - m);
    lg[i] = e;
    atomicAdd(&den[(size_t)seg[row] * HH + h], e);
}

__global__ void scatter_k(const float* __restrict__ e, const float* __restrict__ den,
                          const float* __restrict__ v, const int* __restrict__ seg,
                          float* __restrict__ node, int total)
{
    int i = blockIdx.x * blockDim.x + threadIdx.x;
    if (i >= total) return;
    int row = i >> 7, d = i & 127;
    int nd = seg[row];
    int h = d >> 4;
    float a = __fdividef(e[(size_t)row * HH + h], den[(size_t)nd * HH + h] + 1e-9f);
    atomicAdd(&node[(size_t)nd * DD + d], a * v[i]);
}

__global__ void addback_k(float* __restrict__ x, const float* __restrict__ back,
                          const int* __restrict__ seg, int total)
{
    int i = blockIdx.x * blockDim.x + threadIdx.x;
    if (i >= total) return;
    int row = i >> 7, d = i & 127;
    x[i] += back[(size_t)seg[row] * DD + d];
}

__global__ void headout_k(const float* __restrict__ h2, const float* __restrict__ w3,
                          const float* __restrict__ b3, float* __restrict__ out)
{
    int row = blockIdx.x * 8 + (threadIdx.x >> 5);
    int lane = threadIdx.x & 31;
    if (row >= NNODE) return;
    float4 v = ((const float4*)(h2 + (size_t)row * DD))[lane];
    float4 w = ((const float4*)w3)[lane];
    float p = v.x * w.x + v.y * w.y + v.z * w.z + v.w * w.w;
#pragma unroll
    for (int o = 16; o; o >>= 1) p += __shfl_xor_sync(~0u, p, o);
    if (!lane) out[row] = p + b3[0];
}

/* ------------------------------------------------------------------ */
/* orchestration                                                       */
/* ------------------------------------------------------------------ */
static inline void hgemm(int mode,
    const __half* Ahi, const __half* Alo, const __half* Bhi, const __half* Blo,
    float* C, __half* Chi, __half* Clo,
    const float* bias, const float* aux, int M, int N, int K,
    const __half* B2hi = nullptr, const __half* B2lo = nullptr,
    const float* bias2 = nullptr, int rowsSplit = 0)
{
    dim3 grid((N + 127) / 128, (M + 127) / 128);
    switch (mode) {
        case 0: hgemm_k<0><<<grid, 256, GSMEM>>>(Ahi, Alo, Bhi, Blo, C, Chi, Clo, bias, aux, M, N, K, B2hi, B2lo, bias2, rowsSplit); break;
        case 1: hgemm_k<1><<<grid, 256, GSMEM>>>(Ahi, Alo, Bhi, Blo, C, Chi, Clo, bias, aux, M, N, K, B2hi, B2lo, bias2, rowsSplit); break;
        case 2: hgemm_k<2><<<grid, 256, GSMEM>>>(Ahi, Alo, Bhi, Blo, C, Chi, Clo, bias, aux, M, N, K, B2hi, B2lo, bias2, rowsSplit); break;
        case 3: hgemm_k<3><<<grid, 256, GSMEM>>>(Ahi, Alo, Bhi, Blo, C, Chi, Clo, bias, aux, M, N, K, B2hi, B2lo, bias2, rowsSplit); break;
    }
}

extern "C" void kernel_launch(void* const* d_in, const int* in_sizes, int n_in,
                              void* d_out, int out_size)
{
    cudaFuncSetAttribute(hgemm_k<0>, cudaFuncAttributeMaxDynamicSharedMemorySize, GSMEM);
    cudaFuncSetAttribute(hgemm_k<1>, cudaFuncAttributeMaxDynamicSharedMemorySize, GSMEM);
    cudaFuncSetAttribute(hgemm_k<2>, cudaFuncAttributeMaxDynamicSharedMemorySize, GSMEM);
    cudaFuncSetAttribute(hgemm_k<3>, cudaFuncAttributeMaxDynamicSharedMemorySize, GSMEM);

    int shift = (n_in >= 3 && in_sizes[2] == 1) ? 0 : -1;
#define FIN(i) ((const float*)d_in[(i) >= 3 ? (i) + shift : (i)])
    const float* x_in       = (const float*)d_in[0];
    const int*   walk       = (const int*)d_in[1];
    const float* gru_norm_w = FIN(3);
    const float* wi_f = FIN(4),  *wh_f = FIN(5),  *bi_f = FIN(6),  *bh_f = FIN(7);
    const float* wi_b = FIN(8),  *wh_b = FIN(9),  *bi_b = FIN(10), *bh_b = FIN(11);
    const float* gru_out_w = FIN(12);
    const float* ffn_norm_w = FIN(13);
    const float* w1 = FIN(14), *w2 = FIN(15), *w3 = FIN(16);
    const float* logit_w = FIN(17), *logit_b = FIN(18);
    const float* to_w = FIN(19), *to_b = FIN(20);
    const float* fr_w = FIN(21), *fr_b = FIN(22);
    const float* hw1 = FIN(23), *hb1 = FIN(24);
    const float* hw2 = FIN(25), *hb2 = FIN(26);
    const float* hw3 = FIN(27), *hb3 = FIN(28);
#undef FIN

    float *px, *pxf, *pxb, *phs, *pg, *pe, *pden, *pnode, *pback, *pt2;
    unsigned* pmenc;
    __half *phh, *phl, *phsh, *phsl, *pyh, *pyl;
    __half *pnh, *pnl, *pt1h, *pt1l, *pwh, *pwl;
    cudaGetSymbolAddress((void**)&px,   g_x);
    cudaGetSymbolAddress((void**)&pxf,  g_xf);
    cudaGetSymbolAddress((void**)&pxb,  g_xb);
    cudaGetSymbolAddress((void**)&phs,  g_hs);
    cudaGetSymbolAddress((void**)&pg,   g_g);
    cudaGetSymbolAddress((void**)&pe,   g_e);
    cudaGetSymbolAddress((void**)&pmenc, g_menc);
    cudaGetSymbolAddress((void**)&pden, g_den);
    cudaGetSymbolAddress((void**)&pnode, g_node);
    cudaGetSymbolAddress((void**)&pback, g_back);
    cudaGetSymbolAddress((void**)&pt2,  g_t2);
    cudaGetSymbolAddress((void**)&phh,  g_hh);
    cudaGetSymbolAddress((void**)&phl,  g_hl);
    cudaGetSymbolAddress((void**)&phsh, g_hsh);
    cudaGetSymbolAddress((void**)&phsl, g_hsl);
    cudaGetSymbolAddress((void**)&pyh,  g_yh);
    cudaGetSymbolAddress((void**)&pyl,  g_yl);
    cudaGetSymbolAddress((void**)&pnh,  g_nh);
    cudaGetSymbolAddress((void**)&pnl,  g_nl);
    cudaGetSymbolAddress((void**)&pt1h, g_t1h);
    cudaGetSymbolAddress((void**)&pt1l, g_t1l);
    cudaGetSymbolAddress((void**)&pwh,  g_wh);
    cudaGetSymbolAddress((void**)&pwl,  g_wl);

    /* lifetime aliases: */
    float* pv   = pxf;                                  /* v over dead g1 aux   */
    __half* puh = (__half*)pxb;                         /* u.hi over dead xi_b  */
    __half* pul = (__half*)pxb + (size_t)WL * FHID;     /* u.lo                 */
    __half* pxh = pyh;                                  /* x.hi over dead y.hi  */
    __half* pxl = pyl;                                  /* x.lo over dead y.lo  */

    /* split all weights into half hi/lo pools */
    struct { const float* s; int off; int n; } ws[] = {
        { wi_f, O_WIF, FHID * DD }, { wi_b, O_WIB, FHID * DD },
        { wh_f, O_WHF, FHID * DD }, { wh_b, O_WHB, FHID * DD },
        { gru_out_w, O_GO, DD * 2 * DD },
        { w1, O_W1, FHID * DD }, { w2, O_W2, DD * FHID }, { w3, O_W3, FHID * DD },
        { to_w, O_TO, DD * DD }, { fr_w, O_FR, DD * DD },
        { hw1, O_HW1, DD * DD }, { hw2, O_HW2, DD * DD },
    };
    for (int i = 0; i < 12; i++)
        split_k<<<(ws[i].n + 255) / 256, 256>>>(ws[i].s, pwh + ws[i].off, pwl + ws[i].off, ws[i].n);

    cudaMemcpyAsync(px, x_in, (size_t)WL * DD * sizeof(float), cudaMemcpyDeviceToDevice);

    const int totWH = WL * HH;
    const int totWD = WL * DD;

    for (int t = 0; t < 2; t++) {
        /* ---- Bidirectional GRU block ---- */
        rmsnorm_k<<<WL / 8, 256>>>(px, gru_norm_w, phh, phl, WL);
        hgemm(0, phh, phl, pwh + O_WIF, pwl + O_WIF, pxf, nullptr, nullptr, bi_f, nullptr, WL, FHID, DD);
        hgemm(0, phh, phl, pwh + O_WIB, pwl + O_WIB, pxb, nullptr, nullptr, bi_b, nullptr, WL, FHID, DD);

        cudaMemsetAsync(phs,  0, (size_t)2 * WWLK * DD * sizeof(float));
        cudaMemsetAsync(phsh, 0, (size_t)2 * WWLK * DD * sizeof(__half));
        cudaMemsetAsync(phsl, 0, (size_t)2 * WWLK * DD * sizeof(__half));
        for (int step = 0; step < LSEQ; step++) {
            hgemm(0, phsh, phsl, pwh + O_WHF, pwl + O_WHF, pg, nullptr, nullptr,
                  bh_f, nullptr, 2 * WWLK, FHID, DD,
                  pwh + O_WHB, pwl + O_WHB, bh_b, WWLK);
            gru_gates_k<<<(2 * WWLK * DD + 255) / 256, 256>>>(
                pxf, pxb, pg, phs, phsh, phsl, pyh, pyl, step);
        }
        hgemm(1, pyh, pyl, pwh + O_GO, pwl + O_GO, px, nullptr, nullptr,
              nullptr, nullptr, WL, DD, 2 * DD);

        /* ---- FFN ---- */
        rmsnorm_k<<<WL / 8, 256>>>(px, ffn_norm_w, phh, phl, WL);
        hgemm(0, phh, phl, pwh + O_W1, pwl + O_W1, pxf, nullptr, nullptr,
              nullptr, nullptr, WL, FHID, DD);
        hgemm(3, phh, phl, pwh + O_W3, pwl + O_W3, nullptr, puh, pul,
              nullptr, pxf, WL, FHID, DD);
        hgemm(1, puh, pul, pwh + O_W2, pwl + O_W2, px, pxh, pxl,
              nullptr, nullptr, WL, DD, FHID);

        /* ---- attention scatter ---- */
        logits_k<<<WL / 8, 256>>>(px, logit_w, logit_b, pe, WL);
        cudaMemsetAsync(pmenc, 0, (size_t)NNODE * HH * sizeof(unsigned));
        cudaMemsetAsync(pden,  0, (size_t)NNODE * HH * sizeof(float));
        cudaMemsetAsync(pnode, 0, (size_t)NNODE * DD * sizeof(float));
        segmax_k<<<(totWH + 255) / 256, 256>>>(pe, walk, pmenc, totWH);
        expden_k<<<(totWH + 255) / 256, 256>>>(pe, walk, pmenc, pden, totWH);
        hgemm(0, pxh, pxl, pwh + O_TO, pwl + O_TO, pv, nullptr, nullptr,
              to_b, nullptr, WL, DD, DD);
        scatter_k<<<(totWD + 255) / 256, 256>>>(pe, pden, pv, walk, pnode, totWD);
        split_k<<<(NNODE * DD + 255) / 256, 256>>>(pnode, pnh, pnl, NNODE * DD);
        hgemm(0, pnh, pnl, pwh + O_FR, pwl + O_FR, pback, nullptr, nullptr,
              fr_b, nullptr, NNODE, DD, DD);
        addback_k<<<(totWD + 255) / 256, 256>>>(px, pback, walk, totWD);
    }

    /* ---- scoring head ---- */
    hgemm(2, pnh, pnl, pwh + O_HW1, pwl + O_HW1, nullptr, pt1h, pt1l,
          hb1, nullptr, NNODE, DD, DD);
    hgemm(2, pt1h, pt1l, pwh + O_HW2, pwl + O_HW2, pt2, nullptr, nullptr,
          hb2, nullptr, NNODE, DD, DD);
    headout_k<<<(NNODE + 7) / 8, 256>>>(pt2, hw3, hb3, (float*)d_out);
}